// round 2
// baseline (speedup 1.0000x reference)
#include <cuda_runtime.h>
#include <cuda_bf16.h>

#define N_NODES 25000
#define N_EDGES 400000
#define DF      128
#define N_GRAPHS 512
#define D_OUT   10

// ---------------- scratch (device globals; no runtime alloc allowed) --------
__device__ __align__(16) int   g_deg[N_NODES];
__device__ __align__(16) int   g_rowptr[N_NODES + 1];
__device__ __align__(16) int   g_cursor[N_NODES];
__device__ __align__(16) int   g_esrc[N_EDGES];
__device__ __align__(16) float g_agg[N_NODES * DF];
__device__ __align__(16) float g_h0[N_NODES * DF];
__device__ __align__(16) float g_h1[N_NODES * DF];
__device__ __align__(16) float g_pooled[N_GRAPHS * DF];
__device__ __align__(16) float g_gcount[N_GRAPHS];

// ---------------- zero scratch that gets accumulated into --------------------
__global__ void zero_kernel() {
    int i = blockIdx.x * blockDim.x + threadIdx.x;
    if (i < N_NODES) g_deg[i] = 0;
    if (i < N_GRAPHS) g_gcount[i] = 0.f;
    if (i < N_GRAPHS * DF) g_pooled[i] = 0.f;
}

// ---------------- CSR build: histogram -> scan -> scatter --------------------
__global__ void hist_kernel(const int* __restrict__ dst) {
    int e = blockIdx.x * blockDim.x + threadIdx.x;
    if (e < N_EDGES) atomicAdd(&g_deg[dst[e]], 1);
}

__global__ void scan_kernel() {
    __shared__ int warp_sums[32];
    __shared__ int s_base;
    int t = threadIdx.x, lane = t & 31, w = t >> 5;
    if (t == 0) s_base = 0;
    __syncthreads();
    for (int base = 0; base < N_NODES; base += 1024) {
        int i = base + t;
        int v = (i < N_NODES) ? g_deg[i] : 0;
        int x = v;
        #pragma unroll
        for (int off = 1; off < 32; off <<= 1) {
            int y = __shfl_up_sync(0xFFFFFFFFu, x, off);
            if (lane >= off) x += y;
        }
        if (lane == 31) warp_sums[w] = x;
        __syncthreads();
        if (w == 0) {
            int s = warp_sums[lane];
            #pragma unroll
            for (int off = 1; off < 32; off <<= 1) {
                int y = __shfl_up_sync(0xFFFFFFFFu, s, off);
                if (lane >= off) s += y;
            }
            warp_sums[lane] = s;
        }
        __syncthreads();
        int warp_off = (w > 0) ? warp_sums[w - 1] : 0;
        int excl = x - v + warp_off;
        int rp = s_base + excl;
        if (i < N_NODES) { g_rowptr[i] = rp; g_cursor[i] = rp; }
        int total = warp_sums[31];
        __syncthreads();
        if (t == 0) s_base += total;
        __syncthreads();
    }
    if (threadIdx.x == 0) g_rowptr[N_NODES] = s_base;
}

__global__ void scatter_kernel(const int* __restrict__ src,
                               const int* __restrict__ dst) {
    int e = blockIdx.x * blockDim.x + threadIdx.x;
    if (e < N_EDGES) {
        int d = dst[e];
        int p = atomicAdd(&g_cursor[d], 1);
        g_esrc[p] = src[e];
    }
}

// ---------------- GIN aggregation: one warp per node, float4 lanes ----------
__global__ void agg_kernel(const float* __restrict__ h,
                           const float* __restrict__ eps, int layer) {
    int warp = (blockIdx.x * blockDim.x + threadIdx.x) >> 5;
    int lane = threadIdx.x & 31;
    if (warp >= N_NODES) return;
    float se = 1.0f + eps[layer];
    const float4* h4 = (const float4*)h;
    float4 acc = h4[(size_t)warp * 32 + lane];
    acc.x *= se; acc.y *= se; acc.z *= se; acc.w *= se;
    int e = g_rowptr[warp];
    int end = g_rowptr[warp + 1];
    for (; e + 4 <= end; e += 4) {
        int s0 = g_esrc[e], s1 = g_esrc[e + 1], s2 = g_esrc[e + 2], s3 = g_esrc[e + 3];
        float4 v0 = h4[(size_t)s0 * 32 + lane];
        float4 v1 = h4[(size_t)s1 * 32 + lane];
        float4 v2 = h4[(size_t)s2 * 32 + lane];
        float4 v3 = h4[(size_t)s3 * 32 + lane];
        acc.x += v0.x + v1.x + v2.x + v3.x;
        acc.y += v0.y + v1.y + v2.y + v3.y;
        acc.z += v0.z + v1.z + v2.z + v3.z;
        acc.w += v0.w + v1.w + v2.w + v3.w;
    }
    for (; e < end; e++) {
        int s = g_esrc[e];
        float4 v = h4[(size_t)s * 32 + lane];
        acc.x += v.x; acc.y += v.y; acc.z += v.z; acc.w += v.w;
    }
    ((float4*)g_agg)[(size_t)warp * 32 + lane] = acc;
}

// ---------------- fused MLP: Linear->BN->ReLU->Linear->ReLU ------------------
#define TM 64
#define AS_LD (TM + 4)
#define MLP_SMEM_BYTES ((128 * AS_LD + 128 * 128) * 4)

__global__ __launch_bounds__(256) void mlp_kernel(
    float* __restrict__ hout,
    const float* __restrict__ W1, const float* __restrict__ b1v,
    const float* __restrict__ gammav, const float* __restrict__ betav,
    const float* __restrict__ rmeanv, const float* __restrict__ rvarv,
    const float* __restrict__ W2, const float* __restrict__ b2v)
{
    extern __shared__ float smem[];
    float* As = smem;                 // [128][AS_LD]  A^T: [k][row]
    float* Ws = smem + 128 * AS_LD;   // [128][128]
    __shared__ float sc[128], sh[128], sb2[128];

    int tid = threadIdx.x;
    int row0 = blockIdx.x * TM;

    if (tid < 128) {
        float s = gammav[tid] * rsqrtf(rvarv[tid] + 1e-5f);
        sc[tid] = s;
        sh[tid] = (b1v[tid] - rmeanv[tid]) * s + betav[tid];
        sb2[tid] = b2v[tid];
    }

    // Load agg tile transposed into smem (zero-pad out-of-range rows).
    int lr = tid >> 5, lc = tid & 31;
    #pragma unroll
    for (int p = 0; p < TM / 8; p++) {
        int r = p * 8 + lr;
        int gidx = row0 + r;
        float4 v = make_float4(0.f, 0.f, 0.f, 0.f);
        if (gidx < N_NODES) v = ((const float4*)g_agg)[(size_t)gidx * 32 + lc];
        As[(lc * 4 + 0) * AS_LD + r] = v.x;
        As[(lc * 4 + 1) * AS_LD + r] = v.y;
        As[(lc * 4 + 2) * AS_LD + r] = v.z;
        As[(lc * 4 + 3) * AS_LD + r] = v.w;
    }
    {
        const float4* wsrc = (const float4*)W1;
        float4* wdst = (float4*)Ws;
        #pragma unroll
        for (int i = tid; i < 4096; i += 256) wdst[i] = wsrc[i];
    }
    __syncthreads();

    int tx = tid & 15;   // col group: cols tx*8 .. tx*8+7
    int ty = tid >> 4;   // row group: rows ty*4 .. ty*4+3

    float acc[4][8];
    #pragma unroll
    for (int r = 0; r < 4; r++)
        #pragma unroll
        for (int i = 0; i < 8; i++) acc[r][i] = 0.f;

    #pragma unroll 8
    for (int k = 0; k < 128; k++) {
        float4 a   = *(const float4*)&As[k * AS_LD + ty * 4];
        float4 b0  = *(const float4*)&Ws[k * 128 + tx * 8];
        float4 b1f = *(const float4*)&Ws[k * 128 + tx * 8 + 4];
        float av[4] = {a.x, a.y, a.z, a.w};
        float bv[8] = {b0.x, b0.y, b0.z, b0.w, b1f.x, b1f.y, b1f.z, b1f.w};
        #pragma unroll
        for (int r = 0; r < 4; r++)
            #pragma unroll
            for (int i = 0; i < 8; i++) acc[r][i] += av[r] * bv[i];
    }

    // epilogue 1: BN (eval stats) + ReLU -> z (regs)
    float z[4][8];
    #pragma unroll
    for (int i = 0; i < 8; i++) {
        int j = tx * 8 + i;
        float s = sc[j], t = sh[j];
        #pragma unroll
        for (int r = 0; r < 4; r++)
            z[r][i] = fmaxf(acc[r][i] * s + t, 0.f);
    }
    __syncthreads();   // all GEMM1 smem reads complete

    // store z transposed into As; load W2 into Ws
    #pragma unroll
    for (int i = 0; i < 8; i++)
        #pragma unroll
        for (int r = 0; r < 4; r++)
            As[(tx * 8 + i) * AS_LD + ty * 4 + r] = z[r][i];
    {
        const float4* wsrc = (const float4*)W2;
        float4* wdst = (float4*)Ws;
        #pragma unroll
        for (int i = tid; i < 4096; i += 256) wdst[i] = wsrc[i];
    }
    __syncthreads();

    #pragma unroll
    for (int r = 0; r < 4; r++)
        #pragma unroll
        for (int i = 0; i < 8; i++) acc[r][i] = 0.f;

    #pragma unroll 8
    for (int k = 0; k < 128; k++) {
        float4 a   = *(const float4*)&As[k * AS_LD + ty * 4];
        float4 b0  = *(const float4*)&Ws[k * 128 + tx * 8];
        float4 b1f = *(const float4*)&Ws[k * 128 + tx * 8 + 4];
        float av[4] = {a.x, a.y, a.z, a.w};
        float bv[8] = {b0.x, b0.y, b0.z, b0.w, b1f.x, b1f.y, b1f.z, b1f.w};
        #pragma unroll
        for (int r = 0; r < 4; r++)
            #pragma unroll
            for (int i = 0; i < 8; i++) acc[r][i] += av[r] * bv[i];
    }

    // epilogue 2: +b2, ReLU, coalesced store
    #pragma unroll
    for (int i = 0; i < 8; i++) {
        int j = tx * 8 + i;
        float b = sb2[j];
        #pragma unroll
        for (int r = 0; r < 4; r++)
            acc[r][i] = fmaxf(acc[r][i] + b, 0.f);
    }
    #pragma unroll
    for (int r = 0; r < 4; r++) {
        int gidx = row0 + ty * 4 + r;
        if (gidx < N_NODES) {
            float4 o0 = make_float4(acc[r][0], acc[r][1], acc[r][2], acc[r][3]);
            float4 o1 = make_float4(acc[r][4], acc[r][5], acc[r][6], acc[r][7]);
            ((float4*)hout)[(size_t)gidx * 32 + tx * 2]     = o0;
            ((float4*)hout)[(size_t)gidx * 32 + tx * 2 + 1] = o1;
        }
    }
}

// ---------------- pooling + head ---------------------------------------------
__global__ void count_kernel(const int* __restrict__ batch) {
    int i = blockIdx.x * blockDim.x + threadIdx.x;
    if (i < N_NODES) atomicAdd(&g_gcount[batch[i]], 1.0f);
}

__global__ void poolsum_kernel(const float* __restrict__ h,
                               const int* __restrict__ batch) {
    int idx = blockIdx.x * blockDim.x + threadIdx.x;
    if (idx >= N_NODES * DF) return;
    int n = idx >> 7, d = idx & 127;
    int g = batch[n];
    atomicAdd(&g_pooled[g * DF + d], h[idx]);
}

__global__ void out_kernel(const float* __restrict__ Wout,
                           const float* __restrict__ bout,
                           float* __restrict__ out) {
    int idx = blockIdx.x * blockDim.x + threadIdx.x;
    if (idx >= N_GRAPHS * D_OUT) return;
    int g = idx / D_OUT, o = idx - g * D_OUT;
    const float* p = &g_pooled[g * DF];
    float s = 0.f;
    #pragma unroll 8
    for (int d = 0; d < DF; d++) s += p[d] * Wout[d * D_OUT + o];
    float inv = 1.0f / fmaxf(g_gcount[g], 1.0f);
    out[idx] = fmaf(s, inv, bout[o]);
}

// ---------------- launch ------------------------------------------------------
extern "C" void kernel_launch(void* const* d_in, const int* in_sizes, int n_in,
                              void* d_out, int out_size) {
    const float* x     = (const float*)d_in[0];
    const int*   ei    = (const int*)d_in[1];     // [2][N_EDGES], int32
    const int*   batch = (const int*)d_in[2];     // int32
    const float* W1    = (const float*)d_in[3];
    const float* b1    = (const float*)d_in[4];
    const float* gamma = (const float*)d_in[5];
    const float* beta  = (const float*)d_in[6];
    const float* rmean = (const float*)d_in[7];
    const float* rvar  = (const float*)d_in[8];
    const float* W2    = (const float*)d_in[9];
    const float* b2    = (const float*)d_in[10];
    const float* eps   = (const float*)d_in[11];
    const float* Wout  = (const float*)d_in[12];
    const float* bout  = (const float*)d_in[13];
    float* out = (float*)d_out;

    cudaFuncSetAttribute(mlp_kernel, cudaFuncAttributeMaxDynamicSharedMemorySize,
                         MLP_SMEM_BYTES);

    float *h0_dev, *h1_dev;
    cudaGetSymbolAddress((void**)&h0_dev, g_h0);
    cudaGetSymbolAddress((void**)&h1_dev, g_h1);

    const int* src = ei;
    const int* dst = ei + N_EDGES;

    zero_kernel<<<(N_GRAPHS * DF + 255) / 256, 256>>>();
    hist_kernel<<<(N_EDGES + 255) / 256, 256>>>(dst);
    scan_kernel<<<1, 1024>>>();
    scatter_kernel<<<(N_EDGES + 255) / 256, 256>>>(src, dst);

    const float* hin = x;
    int mlp_blocks = (N_NODES + TM - 1) / TM;
    for (int l = 0; l < 3; l++) {
        agg_kernel<<<(N_NODES * 32 + 255) / 256, 256>>>(hin, eps, l);
        float* ho = (l & 1) ? h1_dev : h0_dev;
        mlp_kernel<<<mlp_blocks, 256, MLP_SMEM_BYTES>>>(
            ho,
            W1 + (size_t)l * DF * DF, b1 + l * DF, gamma + l * DF, beta + l * DF,
            rmean + l * DF, rvar + l * DF, W2 + (size_t)l * DF * DF, b2 + l * DF);
        hin = ho;
    }

    count_kernel<<<(N_NODES + 255) / 256, 256>>>(batch);
    poolsum_kernel<<<(N_NODES * DF + 255) / 256, 256>>>(hin, batch);
    out_kernel<<<(N_GRAPHS * D_OUT + 127) / 128, 128>>>(Wout, bout, out);
}

// round 3
// speedup vs baseline: 1.0971x; 1.0971x over previous
#include <cuda_runtime.h>
#include <cuda_bf16.h>

#define N_NODES 25000
#define N_EDGES 400000
#define DF      128
#define N_GRAPHS 512
#define D_OUT   10

typedef unsigned long long ull;

// ---------------- scratch (device globals; no runtime alloc allowed) --------
__device__ __align__(16) int   g_deg[N_NODES];
__device__ __align__(16) int   g_rowptr[N_NODES + 1];
__device__ __align__(16) int   g_cursor[N_NODES];
__device__ __align__(16) int   g_esrc[N_EDGES];
__device__ __align__(16) float g_agg[N_NODES * DF];
__device__ __align__(16) float g_h0[N_NODES * DF];
__device__ __align__(16) float g_h1[N_NODES * DF];

// ---------------- packed fp32x2 helpers --------------------------------------
#define FMA_F32X2(d, a, b) \
    asm("fma.rn.f32x2 %0, %1, %2, %0;" : "+l"(d) : "l"(a), "l"(b))
#define PACK_DUP(out, v) \
    asm("mov.b64 %0, {%1, %1};" : "=l"(out) : "r"(__float_as_uint(v)))
#define UNPACK2(lo, hi, in) \
    asm("mov.b64 {%0, %1}, %2;" : "=r"(lo), "=r"(hi) : "l"(in))

// ---------------- zero degree array ------------------------------------------
__global__ void zero_kernel() {
    int i = blockIdx.x * blockDim.x + threadIdx.x;
    if (i < N_NODES) g_deg[i] = 0;
}

// ---------------- CSR build: histogram -> scan -> scatter --------------------
__global__ void hist_kernel(const int* __restrict__ dst) {
    int e = blockIdx.x * blockDim.x + threadIdx.x;
    if (e < N_EDGES) atomicAdd(&g_deg[dst[e]], 1);
}

__global__ void scan_kernel() {
    __shared__ int warp_sums[32];
    __shared__ int s_base;
    int t = threadIdx.x, lane = t & 31, w = t >> 5;
    if (t == 0) s_base = 0;
    __syncthreads();
    for (int base = 0; base < N_NODES; base += 1024) {
        int i = base + t;
        int v = (i < N_NODES) ? g_deg[i] : 0;
        int x = v;
        #pragma unroll
        for (int off = 1; off < 32; off <<= 1) {
            int y = __shfl_up_sync(0xFFFFFFFFu, x, off);
            if (lane >= off) x += y;
        }
        if (lane == 31) warp_sums[w] = x;
        __syncthreads();
        if (w == 0) {
            int s = warp_sums[lane];
            #pragma unroll
            for (int off = 1; off < 32; off <<= 1) {
                int y = __shfl_up_sync(0xFFFFFFFFu, s, off);
                if (lane >= off) s += y;
            }
            warp_sums[lane] = s;
        }
        __syncthreads();
        int warp_off = (w > 0) ? warp_sums[w - 1] : 0;
        int excl = x - v + warp_off;
        int rp = s_base + excl;
        if (i < N_NODES) { g_rowptr[i] = rp; g_cursor[i] = rp; }
        int total = warp_sums[31];
        __syncthreads();
        if (t == 0) s_base += total;
        __syncthreads();
    }
    if (threadIdx.x == 0) g_rowptr[N_NODES] = s_base;
}

__global__ void scatter_kernel(const int* __restrict__ src,
                               const int* __restrict__ dst) {
    int e = blockIdx.x * blockDim.x + threadIdx.x;
    if (e < N_EDGES) {
        int d = dst[e];
        int p = atomicAdd(&g_cursor[d], 1);
        g_esrc[p] = src[e];
    }
}

// ---------------- GIN aggregation: one warp per node, float4 lanes ----------
__global__ void agg_kernel(const float* __restrict__ h,
                           const float* __restrict__ eps, int layer) {
    int warp = (blockIdx.x * blockDim.x + threadIdx.x) >> 5;
    int lane = threadIdx.x & 31;
    if (warp >= N_NODES) return;
    float se = 1.0f + eps[layer];
    const float4* h4 = (const float4*)h;
    float4 acc = h4[(size_t)warp * 32 + lane];
    acc.x *= se; acc.y *= se; acc.z *= se; acc.w *= se;
    int e = g_rowptr[warp];
    int end = g_rowptr[warp + 1];
    for (; e + 4 <= end; e += 4) {
        int s0 = g_esrc[e], s1 = g_esrc[e + 1], s2 = g_esrc[e + 2], s3 = g_esrc[e + 3];
        float4 v0 = h4[(size_t)s0 * 32 + lane];
        float4 v1 = h4[(size_t)s1 * 32 + lane];
        float4 v2 = h4[(size_t)s2 * 32 + lane];
        float4 v3 = h4[(size_t)s3 * 32 + lane];
        acc.x += v0.x + v1.x + v2.x + v3.x;
        acc.y += v0.y + v1.y + v2.y + v3.y;
        acc.z += v0.z + v1.z + v2.z + v3.z;
        acc.w += v0.w + v1.w + v2.w + v3.w;
    }
    for (; e < end; e++) {
        int s = g_esrc[e];
        float4 v = h4[(size_t)s * 32 + lane];
        acc.x += v.x; acc.y += v.y; acc.z += v.z; acc.w += v.w;
    }
    ((float4*)g_agg)[(size_t)warp * 32 + lane] = acc;
}

// ---------------- fused MLP: Linear->BN->ReLU->Linear->ReLU ------------------
// A row-major in smem (no transpose, conflict-free fill), FFMA2 inner loop.
#define TM 64
#define A_LD 132   // 128 + 4 floats pad
#define MLP_SMEM_BYTES ((TM * A_LD + 128 * 128) * 4)

__global__ __launch_bounds__(256) void mlp_kernel(
    float* __restrict__ hout,
    const float* __restrict__ W1, const float* __restrict__ b1v,
    const float* __restrict__ gammav, const float* __restrict__ betav,
    const float* __restrict__ rmeanv, const float* __restrict__ rvarv,
    const float* __restrict__ W2, const float* __restrict__ b2v)
{
    extern __shared__ float smem[];
    float* As = smem;                // [TM][A_LD] row-major
    float* Ws = smem + TM * A_LD;    // [128][128] row-major [k][n]
    __shared__ float sc[128], sh[128], sb2[128];

    int tid = threadIdx.x;
    int row0 = blockIdx.x * TM;

    if (tid < 128) {
        float s = gammav[tid] * rsqrtf(rvarv[tid] + 1e-5f);
        sc[tid] = s;
        sh[tid] = (b1v[tid] - rmeanv[tid]) * s + betav[tid];
        sb2[tid] = b2v[tid];
    }

    // Fill As row-major: straight coalesced copy (2048 float4s).
    #pragma unroll
    for (int p = 0; p < 8; p++) {
        int idx = p * 256 + tid;          // 0..2047
        int r = idx >> 5, c4 = idx & 31;  // row, float4-col
        int gidx = row0 + r;
        float4 v = make_float4(0.f, 0.f, 0.f, 0.f);
        if (gidx < N_NODES) v = ((const float4*)g_agg)[(size_t)gidx * 32 + c4];
        *(float4*)&As[r * A_LD + c4 * 4] = v;
    }
    // Fill Ws: straight copy of W1 [k][n].
    {
        const float4* wsrc = (const float4*)W1;
        float4* wdst = (float4*)Ws;
        #pragma unroll
        for (int i = tid; i < 4096; i += 256) wdst[i] = wsrc[i];
    }
    __syncthreads();

    int tx = tid & 15;   // col group: cols tx*8 .. tx*8+7 (4 packed pairs)
    int ty = tid >> 4;   // row group: rows ty*4 .. ty*4+3

    const float* a0p = &As[(ty * 4 + 0) * A_LD];
    const float* a1p = &As[(ty * 4 + 1) * A_LD];
    const float* a2p = &As[(ty * 4 + 2) * A_LD];
    const float* a3p = &As[(ty * 4 + 3) * A_LD];

    ull acc[4][4];
    #pragma unroll
    for (int r = 0; r < 4; r++)
        #pragma unroll
        for (int j = 0; j < 4; j++) acc[r][j] = 0ULL;

    #pragma unroll 4
    for (int k = 0; k < 128; k++) {
        ull a2[4];
        PACK_DUP(a2[0], a0p[k]);
        PACK_DUP(a2[1], a1p[k]);
        PACK_DUP(a2[2], a2p[k]);
        PACK_DUP(a2[3], a3p[k]);
        ulonglong2 bb0 = *(const ulonglong2*)&Ws[k * 128 + tx * 8];
        ulonglong2 bb1 = *(const ulonglong2*)&Ws[k * 128 + tx * 8 + 4];
        ull bv[4] = {bb0.x, bb0.y, bb1.x, bb1.y};
        #pragma unroll
        for (int r = 0; r < 4; r++)
            #pragma unroll
            for (int j = 0; j < 4; j++)
                FMA_F32X2(acc[r][j], a2[r], bv[j]);
    }

    // epilogue 1: BN (eval stats) + ReLU -> z
    float z[4][8];
    #pragma unroll
    for (int r = 0; r < 4; r++)
        #pragma unroll
        for (int j = 0; j < 4; j++) {
            unsigned lo, hi;
            UNPACK2(lo, hi, acc[r][j]);
            int c0 = tx * 8 + 2 * j, c1 = c0 + 1;
            z[r][2 * j]     = fmaxf(fmaf(__uint_as_float(lo), sc[c0], sh[c0]), 0.f);
            z[r][2 * j + 1] = fmaxf(fmaf(__uint_as_float(hi), sc[c1], sh[c1]), 0.f);
        }
    __syncthreads();   // all GEMM1 smem reads complete

    // store z row-major into As; load W2 into Ws
    #pragma unroll
    for (int r = 0; r < 4; r++) {
        float* dstp = &As[(ty * 4 + r) * A_LD + tx * 8];
        *(float4*)dstp       = make_float4(z[r][0], z[r][1], z[r][2], z[r][3]);
        *(float4*)(dstp + 4) = make_float4(z[r][4], z[r][5], z[r][6], z[r][7]);
    }
    {
        const float4* wsrc = (const float4*)W2;
        float4* wdst = (float4*)Ws;
        #pragma unroll
        for (int i = tid; i < 4096; i += 256) wdst[i] = wsrc[i];
    }
    __syncthreads();

    #pragma unroll
    for (int r = 0; r < 4; r++)
        #pragma unroll
        for (int j = 0; j < 4; j++) acc[r][j] = 0ULL;

    #pragma unroll 4
    for (int k = 0; k < 128; k++) {
        ull a2[4];
        PACK_DUP(a2[0], a0p[k]);
        PACK_DUP(a2[1], a1p[k]);
        PACK_DUP(a2[2], a2p[k]);
        PACK_DUP(a2[3], a3p[k]);
        ulonglong2 bb0 = *(const ulonglong2*)&Ws[k * 128 + tx * 8];
        ulonglong2 bb1 = *(const ulonglong2*)&Ws[k * 128 + tx * 8 + 4];
        ull bv[4] = {bb0.x, bb0.y, bb1.x, bb1.y};
        #pragma unroll
        for (int r = 0; r < 4; r++)
            #pragma unroll
            for (int j = 0; j < 4; j++)
                FMA_F32X2(acc[r][j], a2[r], bv[j]);
    }

    // epilogue 2: +b2, ReLU, coalesced store
    #pragma unroll
    for (int r = 0; r < 4; r++) {
        int gidx = row0 + ty * 4 + r;
        if (gidx < N_NODES) {
            float o[8];
            #pragma unroll
            for (int j = 0; j < 4; j++) {
                unsigned lo, hi;
                UNPACK2(lo, hi, acc[r][j]);
                int c0 = tx * 8 + 2 * j, c1 = c0 + 1;
                o[2 * j]     = fmaxf(__uint_as_float(lo) + sb2[c0], 0.f);
                o[2 * j + 1] = fmaxf(__uint_as_float(hi) + sb2[c1], 0.f);
            }
            float* dstp = &hout[(size_t)gidx * DF + tx * 8];
            *(float4*)dstp       = make_float4(o[0], o[1], o[2], o[3]);
            *(float4*)(dstp + 4) = make_float4(o[4], o[5], o[6], o[7]);
        }
    }
}

// ---------------- fused pool (sorted batch) + head ---------------------------
__global__ __launch_bounds__(128) void pool_out_kernel(
    const float* __restrict__ h, const int* __restrict__ batch,
    const float* __restrict__ Wout, const float* __restrict__ bout,
    float* __restrict__ out)
{
    __shared__ float sp[DF];
    int g = blockIdx.x;
    int t = threadIdx.x;

    // lower_bound(batch, g) and lower_bound(batch, g+1) on sorted batch
    int lo = 0, hi = N_NODES;
    while (lo < hi) { int m = (lo + hi) >> 1; if (batch[m] < g) lo = m + 1; else hi = m; }
    int start = lo;
    hi = N_NODES;
    while (lo < hi) { int m = (lo + hi) >> 1; if (batch[m] < g + 1) lo = m + 1; else hi = m; }
    int end = lo;

    float s = 0.f;
    for (int n = start; n < end; n++) s += h[(size_t)n * DF + t];
    float cnt = (float)(end - start);
    sp[t] = s / fmaxf(cnt, 1.0f);
    __syncthreads();

    if (t < D_OUT) {
        float acc = bout[t];
        #pragma unroll 8
        for (int d = 0; d < DF; d++) acc += sp[d] * Wout[d * D_OUT + t];
        out[g * D_OUT + t] = acc;
    }
}

// ---------------- launch ------------------------------------------------------
extern "C" void kernel_launch(void* const* d_in, const int* in_sizes, int n_in,
                              void* d_out, int out_size) {
    const float* x     = (const float*)d_in[0];
    const int*   ei    = (const int*)d_in[1];     // [2][N_EDGES], int32
    const int*   batch = (const int*)d_in[2];     // int32 (sorted)
    const float* W1    = (const float*)d_in[3];
    const float* b1    = (const float*)d_in[4];
    const float* gamma = (const float*)d_in[5];
    const float* beta  = (const float*)d_in[6];
    const float* rmean = (const float*)d_in[7];
    const float* rvar  = (const float*)d_in[8];
    const float* W2    = (const float*)d_in[9];
    const float* b2    = (const float*)d_in[10];
    const float* eps   = (const float*)d_in[11];
    const float* Wout  = (const float*)d_in[12];
    const float* bout  = (const float*)d_in[13];
    float* out = (float*)d_out;

    cudaFuncSetAttribute(mlp_kernel, cudaFuncAttributeMaxDynamicSharedMemorySize,
                         MLP_SMEM_BYTES);

    float *h0_dev, *h1_dev;
    cudaGetSymbolAddress((void**)&h0_dev, g_h0);
    cudaGetSymbolAddress((void**)&h1_dev, g_h1);

    const int* src = ei;
    const int* dst = ei + N_EDGES;

    zero_kernel<<<(N_NODES + 255) / 256, 256>>>();
    hist_kernel<<<(N_EDGES + 255) / 256, 256>>>(dst);
    scan_kernel<<<1, 1024>>>();
    scatter_kernel<<<(N_EDGES + 255) / 256, 256>>>(src, dst);

    const float* hin = x;
    int mlp_blocks = (N_NODES + TM - 1) / TM;
    for (int l = 0; l < 3; l++) {
        agg_kernel<<<(N_NODES * 32 + 255) / 256, 256>>>(hin, eps, l);
        float* ho = (l & 1) ? h1_dev : h0_dev;
        mlp_kernel<<<mlp_blocks, 256, MLP_SMEM_BYTES>>>(
            ho,
            W1 + (size_t)l * DF * DF, b1 + l * DF, gamma + l * DF, beta + l * DF,
            rmean + l * DF, rvar + l * DF, W2 + (size_t)l * DF * DF, b2 + l * DF);
        hin = ho;
    }

    pool_out_kernel<<<N_GRAPHS, 128>>>(hin, batch, Wout, bout, out);
}

// round 5
// speedup vs baseline: 1.5485x; 1.4115x over previous
#include <cuda_runtime.h>
#include <cuda_bf16.h>
#include <cstdint>

#define N_NODES 25000
#define N_EDGES 400000
#define DF      128
#define N_GRAPHS 512
#define D_OUT   10

// ---------------- scratch (device globals; no runtime alloc allowed) --------
__device__ __align__(16) int   g_deg[N_NODES];
__device__ __align__(16) int   g_rowptr[N_NODES + 1];
__device__ __align__(16) int   g_cursor[N_NODES];
__device__ __align__(16) int   g_esrc[N_EDGES];
__device__ __align__(16) float g_agg[N_NODES * DF];
__device__ __align__(16) float g_h0[N_NODES * DF];
__device__ __align__(16) float g_h1[N_NODES * DF];
// bf16 hi/lo weight images, [n][k] row-major, 6 matrices (layer*2 + {W1,W2})
__device__ __align__(16) unsigned short g_wimg_hi[6 * 16384];
__device__ __align__(16) unsigned short g_wimg_lo[6 * 16384];

// ---------------- helpers -----------------------------------------------------
__device__ __forceinline__ uint32_t smem_to_u32(const void* p) {
    uint32_t a;
    asm("{ .reg .u64 t; cvta.to.shared.u64 t, %1; cvt.u32.u64 %0, t; }"
        : "=r"(a) : "l"(p));
    return a;
}
__device__ __forceinline__ void ldsm_x4(uint32_t* r, uint32_t addr) {
    asm volatile("ldmatrix.sync.aligned.m8n8.x4.shared.b16 {%0,%1,%2,%3}, [%4];"
        : "=r"(r[0]), "=r"(r[1]), "=r"(r[2]), "=r"(r[3]) : "r"(addr));
}
__device__ __forceinline__ void ldsm_x2(uint32_t* r, uint32_t addr) {
    asm volatile("ldmatrix.sync.aligned.m8n8.x2.shared.b16 {%0,%1}, [%2];"
        : "=r"(r[0]), "=r"(r[1]) : "r"(addr));
}
__device__ __forceinline__ void mma_bf16(float* c, const uint32_t* a, const uint32_t* b) {
    asm volatile("mma.sync.aligned.m16n8k16.row.col.f32.bf16.bf16.f32 "
        "{%0,%1,%2,%3}, {%4,%5,%6,%7}, {%8,%9}, {%0,%1,%2,%3};"
        : "+f"(c[0]), "+f"(c[1]), "+f"(c[2]), "+f"(c[3])
        : "r"(a[0]), "r"(a[1]), "r"(a[2]), "r"(a[3]), "r"(b[0]), "r"(b[1]));
}
__device__ __forceinline__ uint32_t bf2_bits(__nv_bfloat162 v) {
    return *reinterpret_cast<uint32_t*>(&v);
}

// ---------------- weight prep: fp32 [k][n] -> bf16 hi/lo images [n][k] ------
__global__ void wprep_kernel(const float* __restrict__ W1,
                             const float* __restrict__ W2) {
    int e = blockIdx.x * blockDim.x + threadIdx.x;
    if (e >= 6 * 16384) return;
    int mat = e >> 14, r = e & 16383;
    int k = r & 127, n = r >> 7;
    int layer = mat >> 1;
    const float* W = (mat & 1) ? W2 : W1;
    float v = W[layer * 16384 + k * 128 + n];
    __nv_bfloat16 hb = __float2bfloat16(v);
    __nv_bfloat16 lb = __float2bfloat16(v - __bfloat162float(hb));
    g_wimg_hi[mat * 16384 + n * 128 + k] = *reinterpret_cast<unsigned short*>(&hb);
    g_wimg_lo[mat * 16384 + n * 128 + k] = *reinterpret_cast<unsigned short*>(&lb);
}

// ---------------- zero degree array ------------------------------------------
__global__ void zero_kernel() {
    int i = blockIdx.x * blockDim.x + threadIdx.x;
    if (i < N_NODES) g_deg[i] = 0;
}

// ---------------- CSR build: histogram -> scan -> scatter --------------------
__global__ void hist_kernel(const int* __restrict__ dst) {
    int e = blockIdx.x * blockDim.x + threadIdx.x;
    if (e < N_EDGES) atomicAdd(&g_deg[dst[e]], 1);
}

__global__ void scan_kernel() {
    __shared__ int warp_sums[32];
    __shared__ int s_base;
    int t = threadIdx.x, lane = t & 31, w = t >> 5;
    if (t == 0) s_base = 0;
    __syncthreads();
    for (int base = 0; base < N_NODES; base += 1024) {
        int i = base + t;
        int v = (i < N_NODES) ? g_deg[i] : 0;
        int x = v;
        #pragma unroll
        for (int off = 1; off < 32; off <<= 1) {
            int y = __shfl_up_sync(0xFFFFFFFFu, x, off);
            if (lane >= off) x += y;
        }
        if (lane == 31) warp_sums[w] = x;
        __syncthreads();
        if (w == 0) {
            int s = warp_sums[lane];
            #pragma unroll
            for (int off = 1; off < 32; off <<= 1) {
                int y = __shfl_up_sync(0xFFFFFFFFu, s, off);
                if (lane >= off) s += y;
            }
            warp_sums[lane] = s;
        }
        __syncthreads();
        int warp_off = (w > 0) ? warp_sums[w - 1] : 0;
        int excl = x - v + warp_off;
        int rp = s_base + excl;
        if (i < N_NODES) { g_rowptr[i] = rp; g_cursor[i] = rp; }
        int total = warp_sums[31];
        __syncthreads();
        if (t == 0) s_base += total;
        __syncthreads();
    }
    if (threadIdx.x == 0) g_rowptr[N_NODES] = s_base;
}

__global__ void scatter_kernel(const int* __restrict__ src,
                               const int* __restrict__ dst) {
    int e = blockIdx.x * blockDim.x + threadIdx.x;
    if (e < N_EDGES) {
        int d = dst[e];
        int p = atomicAdd(&g_cursor[d], 1);
        g_esrc[p] = src[e];
    }
}

// ---------------- GIN aggregation: one warp per node, float4 lanes ----------
__global__ void agg_kernel(const float* __restrict__ h,
                           const float* __restrict__ eps, int layer) {
    int warp = (blockIdx.x * blockDim.x + threadIdx.x) >> 5;
    int lane = threadIdx.x & 31;
    if (warp >= N_NODES) return;
    float se = 1.0f + eps[layer];
    const float4* h4 = (const float4*)h;
    float4 acc = h4[(size_t)warp * 32 + lane];
    acc.x *= se; acc.y *= se; acc.z *= se; acc.w *= se;
    int e = g_rowptr[warp];
    int end = g_rowptr[warp + 1];
    for (; e + 4 <= end; e += 4) {
        int s0 = g_esrc[e], s1 = g_esrc[e + 1], s2 = g_esrc[e + 2], s3 = g_esrc[e + 3];
        float4 v0 = h4[(size_t)s0 * 32 + lane];
        float4 v1 = h4[(size_t)s1 * 32 + lane];
        float4 v2 = h4[(size_t)s2 * 32 + lane];
        float4 v3 = h4[(size_t)s3 * 32 + lane];
        acc.x += v0.x + v1.x + v2.x + v3.x;
        acc.y += v0.y + v1.y + v2.y + v3.y;
        acc.z += v0.z + v1.z + v2.z + v3.z;
        acc.w += v0.w + v1.w + v2.w + v3.w;
    }
    for (; e < end; e++) {
        int s = g_esrc[e];
        float4 v = h4[(size_t)s * 32 + lane];
        acc.x += v.x; acc.y += v.y; acc.z += v.z; acc.w += v.w;
    }
    ((float4*)g_agg)[(size_t)warp * 32 + lane] = acc;
}

// ---------------- HMMA fused MLP (split-bf16, 3-pass) ------------------------
// smem: 6 regions of 128 rows x 136 bf16 (272B rows, conflict-free ldmatrix).
#define A_LD_B   272                      // bytes per padded row
#define SM_AS_HI 0
#define SM_AS_LO 34816
#define SM_W1_HI 69632
#define SM_W1_LO 104448
#define SM_W2_HI 139264
#define SM_W2_LO 174080
#define MLP_SMEM 208896

__global__ __launch_bounds__(256) void mma_mlp_kernel(
    float* __restrict__ hout, int mat1,
    const float* __restrict__ b1v,
    const float* __restrict__ gammav, const float* __restrict__ betav,
    const float* __restrict__ rmeanv, const float* __restrict__ rvarv,
    const float* __restrict__ b2v)
{
    extern __shared__ char sm[];
    __shared__ float sc[128], sh[128], sb2[128];

    int tid = threadIdx.x, wid = tid >> 5, lane = tid & 31;
    int row0 = blockIdx.x * 128;
    uint32_t base = smem_to_u32(sm);

    if (tid < 128) {
        float s = gammav[tid] * rsqrtf(rvarv[tid] + 1e-5f);
        sc[tid] = s;
        sh[tid] = (b1v[tid] - rmeanv[tid]) * s + betav[tid];
        sb2[tid] = b2v[tid];
    }

    // --- A fill: fp32 agg -> bf16 hi/lo, padded rows ------------------------
    for (int i = tid; i < 4096; i += 256) {
        int r = i >> 5, c4 = i & 31;
        int gidx = row0 + r;
        float4 v = make_float4(0.f, 0.f, 0.f, 0.f);
        if (gidx < N_NODES) v = ((const float4*)g_agg)[(size_t)gidx * 32 + c4];
        __nv_bfloat162 h01 = __floats2bfloat162_rn(v.x, v.y);
        __nv_bfloat162 h23 = __floats2bfloat162_rn(v.z, v.w);
        __nv_bfloat162 l01 = __floats2bfloat162_rn(v.x - __bfloat162float(h01.x),
                                                   v.y - __bfloat162float(h01.y));
        __nv_bfloat162 l23 = __floats2bfloat162_rn(v.z - __bfloat162float(h23.x),
                                                   v.w - __bfloat162float(h23.y));
        uint2 uh = make_uint2(bf2_bits(h01), bf2_bits(h23));
        uint2 ul = make_uint2(bf2_bits(l01), bf2_bits(l23));
        *(uint2*)(sm + SM_AS_HI + r * A_LD_B + c4 * 8) = uh;
        *(uint2*)(sm + SM_AS_LO + r * A_LD_B + c4 * 8) = ul;
    }
    // --- W fills: copy 4 images into padded smem ----------------------------
    {
        const float4* s1h = (const float4*)g_wimg_hi + (size_t)mat1 * 2048;
        const float4* s1l = (const float4*)g_wimg_lo + (size_t)mat1 * 2048;
        const float4* s2h = s1h + 2048;
        const float4* s2l = s1l + 2048;
        for (int i = tid; i < 2048; i += 256) {
            int n = i >> 4, c = i & 15;
            int off = n * A_LD_B + c * 16;
            *(float4*)(sm + SM_W1_HI + off) = s1h[i];
            *(float4*)(sm + SM_W1_LO + off) = s1l[i];
            *(float4*)(sm + SM_W2_HI + off) = s2h[i];
            *(float4*)(sm + SM_W2_LO + off) = s2l[i];
        }
    }
    __syncthreads();

    int m0 = wid * 16;
    int lrow = lane & 15, lkoff = (lane >> 4) << 3;          // A ldmatrix addressing
    uint32_t aAddrHi = base + SM_AS_HI + (m0 + lrow) * A_LD_B + lkoff * 2;
    uint32_t aAddrLo = base + SM_AS_LO + (m0 + lrow) * A_LD_B + lkoff * 2;
    int bn = lane & 7, bk = ((lane >> 3) & 1) << 3;          // B ldmatrix addressing

    uint32_t Ah[32], Al[32];
    #pragma unroll
    for (int kk = 0; kk < 8; kk++) {
        ldsm_x4(&Ah[kk * 4], aAddrHi + kk * 32);
        ldsm_x4(&Al[kk * 4], aAddrLo + kk * 32);
    }

    int erow = (lane >> 2);        // 0..7 within warp tile
    int ecl  = (lane & 3) * 2;

    // ---------------- GEMM1 + BN/ReLU/resplit -------------------------------
    #pragma unroll 1
    for (int nt = 0; nt < 16; nt++) {
        float c[4] = {0.f, 0.f, 0.f, 0.f};
        uint32_t bAddrHi = base + SM_W1_HI + (nt * 8 + bn) * A_LD_B + bk * 2;
        uint32_t bAddrLo = base + SM_W1_LO + (nt * 8 + bn) * A_LD_B + bk * 2;
        #pragma unroll
        for (int kk = 0; kk < 8; kk++) {
            uint32_t bh[2], bl[2];
            ldsm_x2(bh, bAddrHi + kk * 32);
            ldsm_x2(bl, bAddrLo + kk * 32);
            mma_bf16(c, &Ah[kk * 4], bh);
            mma_bf16(c, &Ah[kk * 4], bl);
            mma_bf16(c, &Al[kk * 4], bh);
        }
        int col = nt * 8 + ecl;
        float s0 = sc[col], s1 = sc[col + 1], t0 = sh[col], t1 = sh[col + 1];
        #pragma unroll
        for (int half = 0; half < 2; half++) {
            int r = m0 + erow + half * 8;
            float z0 = fmaxf(fmaf(c[half * 2 + 0], s0, t0), 0.f);
            float z1 = fmaxf(fmaf(c[half * 2 + 1], s1, t1), 0.f);
            __nv_bfloat162 zh = __floats2bfloat162_rn(z0, z1);
            __nv_bfloat162 zl = __floats2bfloat162_rn(z0 - __bfloat162float(zh.x),
                                                      z1 - __bfloat162float(zh.y));
            *(uint32_t*)(sm + SM_AS_HI + r * A_LD_B + col * 2) = bf2_bits(zh);
            *(uint32_t*)(sm + SM_AS_LO + r * A_LD_B + col * 2) = bf2_bits(zl);
        }
    }
    __syncwarp();

    // reload A frags (z) — same rows, written by this warp only
    #pragma unroll
    for (int kk = 0; kk < 8; kk++) {
        ldsm_x4(&Ah[kk * 4], aAddrHi + kk * 32);
        ldsm_x4(&Al[kk * 4], aAddrLo + kk * 32);
    }

    // ---------------- GEMM2 + bias/ReLU/store -------------------------------
    #pragma unroll 1
    for (int nt = 0; nt < 16; nt++) {
        float c[4] = {0.f, 0.f, 0.f, 0.f};
        uint32_t bAddrHi = base + SM_W2_HI + (nt * 8 + bn) * A_LD_B + bk * 2;
        uint32_t bAddrLo = base + SM_W2_LO + (nt * 8 + bn) * A_LD_B + bk * 2;
        #pragma unroll
        for (int kk = 0; kk < 8; kk++) {
            uint32_t bh[2], bl[2];
            ldsm_x2(bh, bAddrHi + kk * 32);
            ldsm_x2(bl, bAddrLo + kk * 32);
            mma_bf16(c, &Ah[kk * 4], bh);
            mma_bf16(c, &Ah[kk * 4], bl);
            mma_bf16(c, &Al[kk * 4], bh);
        }
        int col = nt * 8 + ecl;
        float b0 = sb2[col], b1 = sb2[col + 1];
        #pragma unroll
        for (int half = 0; half < 2; half++) {
            int grow = row0 + m0 + erow + half * 8;
            if (grow < N_NODES) {
                float2 ov;
                ov.x = fmaxf(c[half * 2 + 0] + b0, 0.f);
                ov.y = fmaxf(c[half * 2 + 1] + b1, 0.f);
                *(float2*)&hout[(size_t)grow * DF + col] = ov;
            }
        }
    }
}

// ---------------- fused pool (sorted batch) + head ---------------------------
__global__ __launch_bounds__(128) void pool_out_kernel(
    const float* __restrict__ h, const int* __restrict__ batch,
    const float* __restrict__ Wout, const float* __restrict__ bout,
    float* __restrict__ out)
{
    __shared__ float sp[DF];
    int g = blockIdx.x;
    int t = threadIdx.x;

    int lo = 0, hi = N_NODES;
    while (lo < hi) { int m = (lo + hi) >> 1; if (batch[m] < g) lo = m + 1; else hi = m; }
    int start = lo;
    hi = N_NODES;
    while (lo < hi) { int m = (lo + hi) >> 1; if (batch[m] < g + 1) lo = m + 1; else hi = m; }
    int end = lo;

    float s = 0.f;
    for (int n = start; n < end; n++) s += h[(size_t)n * DF + t];
    float cnt = (float)(end - start);
    sp[t] = s / fmaxf(cnt, 1.0f);
    __syncthreads();

    if (t < D_OUT) {
        float acc = bout[t];
        #pragma unroll 8
        for (int d = 0; d < DF; d++) acc += sp[d] * Wout[d * D_OUT + t];
        out[g * D_OUT + t] = acc;
    }
}

// ---------------- launch ------------------------------------------------------
extern "C" void kernel_launch(void* const* d_in, const int* in_sizes, int n_in,
                              void* d_out, int out_size) {
    const float* x     = (const float*)d_in[0];
    const int*   ei    = (const int*)d_in[1];     // [2][N_EDGES], int32
    const int*   batch = (const int*)d_in[2];     // int32 (sorted)
    const float* W1    = (const float*)d_in[3];
    const float* b1    = (const float*)d_in[4];
    const float* gamma = (const float*)d_in[5];
    const float* beta  = (const float*)d_in[6];
    const float* rmean = (const float*)d_in[7];
    const float* rvar  = (const float*)d_in[8];
    const float* W2    = (const float*)d_in[9];
    const float* b2    = (const float*)d_in[10];
    const float* eps   = (const float*)d_in[11];
    const float* Wout  = (const float*)d_in[12];
    const float* bout  = (const float*)d_in[13];
    float* out = (float*)d_out;

    cudaFuncSetAttribute(mma_mlp_kernel, cudaFuncAttributeMaxDynamicSharedMemorySize,
                         MLP_SMEM);

    float *h0_dev, *h1_dev;
    cudaGetSymbolAddress((void**)&h0_dev, g_h0);
    cudaGetSymbolAddress((void**)&h1_dev, g_h1);

    const int* src = ei;
    const int* dst = ei + N_EDGES;

    zero_kernel<<<(N_NODES + 255) / 256, 256>>>();
    hist_kernel<<<(N_EDGES + 255) / 256, 256>>>(dst);
    scan_kernel<<<1, 1024>>>();
    scatter_kernel<<<(N_EDGES + 255) / 256, 256>>>(src, dst);
    wprep_kernel<<<(6 * 16384 + 255) / 256, 256>>>(W1, W2);

    const float* hin = x;
    int mlp_blocks = (N_NODES + 127) / 128;
    for (int l = 0; l < 3; l++) {
        agg_kernel<<<(N_NODES * 32 + 255) / 256, 256>>>(hin, eps, l);
        float* ho = (l & 1) ? h1_dev : h0_dev;
        mma_mlp_kernel<<<mlp_blocks, 256, MLP_SMEM>>>(
            ho, l * 2,
            b1 + l * DF, gamma + l * DF, beta + l * DF,
            rmean + l * DF, rvar + l * DF, b2 + l * DF);
        hin = ho;
    }

    pool_out_kernel<<<N_GRAPHS, 128>>>(hin, batch, Wout, bout, out);
}